// round 7
// baseline (speedup 1.0000x reference)
#include <cuda_runtime.h>
#include <cstdint>

#define N_STFT   1025
#define N_MELS   128
#define BATCH    4
#define TIME     1024
#define ROWS     (BATCH*TIME)
#define MAX_ITER 20
#define LR       0.3f
#define MOM      0.9f
#define INVC     (2.0f/4096.0f)
#define CH       17            // frequency bins per lane (64*17 = 1088 >= 1025)
#define LPR      64            // lanes per row (2 warps)
#define RPB      2             // rows per CTA
#define THREADS  128
#define FPAD     (LPR*CH)      // 1088

// ---------------- device globals ----------------
__device__ float2        g_w01[FPAD];     // (w0,w1) per frequency, zero tail
__device__ unsigned char g_mbt[N_STFT];   // first-nonzero mel per frequency

// ---------------- table build: one warp per frequency ----------------
__global__ void build_tables_k(const float* __restrict__ fb) {
    int gw   = (blockIdx.x * blockDim.x + threadIdx.x) >> 5;
    int lane = threadIdx.x & 31;
    if (gw >= FPAD) return;
    if (gw >= N_STFT) { if (!lane) g_w01[gw] = make_float2(0.f, 0.f); return; }
    const float* r = fb + (size_t)gw * N_MELS;
    int m4 = lane * 4;
    unsigned loc = 128u;
    #pragma unroll
    for (int k = 3; k >= 0; k--) if (r[m4 + k] != 0.f) loc = (unsigned)(m4 + k);
    #pragma unroll
    for (int o = 16; o; o >>= 1) {
        unsigned v = __shfl_xor_sync(0xffffffffu, loc, o);
        loc = v < loc ? v : loc;
    }
    if (!lane) {
        float w0 = 0.f, w1 = 0.f; int mm = 0;
        if (loc < 128u) {
            mm = (int)loc;
            w0 = r[loc];
            w1 = (loc < 127u) ? r[loc + 1] : 0.f;
        }
        g_w01[gw] = make_float2(w0, w1);
        g_mbt[gw] = (unsigned char)mm;
    }
}

// ---------------- asm helpers ----------------
__device__ __forceinline__ unsigned smaddr(const void* p) {
    return (unsigned)__cvta_generic_to_shared(p);
}
__device__ __forceinline__ void sts_f32(unsigned a, float v) {
    asm volatile("st.shared.f32 [%0], %1;" :: "r"(a), "f"(v) : "memory");
}
// acc-cursor control: flush a0 to slot0 of completed mel on change, shift a0<-a1,
// a1<-0, advance acc cursor (pitch 32B = 8 slots). Change flag rides sign(w0).
#define CTRL_A(w0i) asm volatile(                        \
    "{\n\t.reg .pred p;\n\t"                             \
    "setp.lt.f32 p, %3, 0f00000000;\n\t"                 \
    "@p st.shared.f32 [%0], %1;\n\t"                     \
    "selp.f32 %1, %2, %1, p;\n\t"                        \
    "selp.f32 %2, 0f00000000, %2, p;\n\t"                \
    "@p add.u32 %0, %0, 32;\n\t}"                        \
    : "+r"(aaddr), "+f"(a0), "+f"(a1)                    \
    : "f"(w0i) : "memory")
// diff-cursor advance (pitch 8B), decoupled so loads run 2 bins ahead
#define CTRL_D(w0j) asm volatile(                        \
    "{\n\t.reg .pred p;\n\t"                             \
    "setp.lt.f32 p, %1, 0f00000000;\n\t"                 \
    "@p add.u32 %0, %0, 8;\n\t}"                         \
    : "+r"(daddr) : "f"(w0j))
#define LDD(x, y) asm volatile(                          \
    "ld.shared.v2.f32 {%0,%1}, [%2];"                    \
    : "=f"(x), "=f"(y) : "r"(daddr))
#define ROWBAR() asm volatile("bar.sync %0, 64;" :: "r"(rr + 1) : "memory")

// ---------------- shared: iteration phase / epilogue stage union ----------------
// acc slots per mel: 0 = in-loop flush (unique boundary writer),
// 1/2 = a0 end-flush by lane parity, 3/4 = a1 end-flush by lane parity (at mel+1).
struct __align__(16) SmemIter {
    float  acc[RPB][132][8];
    float2 dq[RPB][136];       // dq[r][1+m] = (e[m], e[m+1]); [0] = lead pad
};
union __align__(16) SmemU {
    SmemIter it;
    float    stage[RPB][FPAD];
};

// ---------------- main: 2 warps per (b,t) row; 20 fused iterations ----------------
__global__ void __launch_bounds__(THREADS, 5)
imel_k(const float* __restrict__ mel, const float* __restrict__ spi,
       float* __restrict__ out)
{
    __shared__ SmemU S;
    const int tid  = threadIdx.x;
    const int wid  = tid >> 5;
    const int lane = tid & 31;
    const int rr   = wid >> 1;                 // row within CTA (0/1)
    const int l2   = ((wid & 1) << 5) | lane;  // lane within row (0..63)
    const int row  = blockIdx.x * RPB + rr;
    const int b    = row >> 10;
    const int t    = row & (TIME - 1);

    // one-time zero of acc slots + dq (write pattern static across iterations)
    {
        float4 z = make_float4(0.f, 0.f, 0.f, 0.f);
        float4* pa = reinterpret_cast<float4*>(&S.it.acc[rr][0][0]);
        for (int k = l2; k < 264; k += LPR) pa[k] = z;          // 132*8 floats
        float4* pd = reinterpret_cast<float4*>(&S.it.dq[rr][0]);
        for (int k = l2; k < 68; k += LPR) pd[k] = z;           // 136 float2
    }

    const int f_lo = l2 * CH;

    // register-resident state; sign(w0[i]) = "mel changes between bin i-1 and i"
    float w0[CH], w1[CH], sp[CH], bu[CH];
    int mfirst;
    {
        int pm = 0;
        #pragma unroll
        for (int i = 0; i < CH; i++) {
            int f  = f_lo + i;
            int fc = f > N_STFT-1 ? N_STFT-1 : f;
            float2 w = g_w01[f];                 // zero beyond N_STFT
            sp[i] = spi[(size_t)row * N_STFT + fc];
            bu[i] = 0.f;
            int m = (int)g_mbt[fc];
            if (i == 0) { mfirst = m; pm = m; w0[0] = w.x; }
            else {
                m = m < pm ? pm : m;             // monotone clamp (zero rows/pads)
                w0[i] = (m != pm) ? -w.x : w.x;
                pm = m;
            }
            w1[i] = w.y;
        }
    }
    float melI[2];
    #pragma unroll
    for (int j = 0; j < 2; j++)
        melI[j] = mel[(size_t)b*(N_MELS*TIME) + (size_t)(l2 + 64*j)*TIME + t] * INVC;

    const unsigned accb = smaddr(&S.it.acc[rr][0][0]);
    const unsigned dq0  = smaddr(&S.it.dq[rr][1]);
    const unsigned par  = ((unsigned)l2 & 1u) << 2;
    const unsigned eo0  = 4u  + par;    // a0 end-flush slot (1/2)
    const unsigned eo1  = 44u + par;    // a1 end-flush slot (3/4) at mel+1

    ROWBAR();   // zeros visible across both warps of the row

    // ---- prologue forward: scatter proj of iteration 0 ----
    {
        unsigned aaddr = accb + (unsigned)mfirst * 32u;
        float a0 = 0.f, a1 = 0.f;
        #pragma unroll
        for (int i = 0; i < CH; i++) {
            if (i > 0) CTRL_A(w0[i]);
            float aw = fabsf(w0[i]);
            a0 = fmaf(sp[i], aw,    a0);
            a1 = fmaf(sp[i], w1[i], a1);
        }
        sts_f32(aaddr + eo0, a0);
        sts_f32(aaddr + eo1, a1);
    }
    ROWBAR();

    #pragma unroll 1
    for (int it = 0; it < MAX_ITER; it++) {
        // ---- combine: e[m] = INVC*proj[m] - INVC*mel[m]; write aligned pair rep ----
        #pragma unroll
        for (int j = 0; j < 2; j++) {
            int m = l2 + 64*j;
            float4 v = *reinterpret_cast<const float4*>(&S.it.acc[rr][m][0]);
            float v4 = S.it.acc[rr][m][4];
            float s  = ((v.x + v.y) + (v.z + v.w)) + v4;
            float e  = fmaf(s, INVC, -melI[j]);
            sts_f32(dq0 + (unsigned)m * 8u,      e);   // E2[m].x
            sts_f32(dq0 + (unsigned)m * 8u - 4u, e);   // E2[m-1].y (m=0 -> lead pad)
        }
        ROWBAR();

        // ---- fused backward(it) + forward(it+1); d-loads pipelined 2 bins ahead ----
        unsigned aaddr = accb + (unsigned)mfirst * 32u;
        unsigned daddr = dq0  + (unsigned)mfirst * 8u;
        float a0 = 0.f, a1 = 0.f;
        float dx[CH], dy[CH];
        LDD(dx[0], dy[0]);
        CTRL_D(w0[1]); LDD(dx[1], dy[1]);
        #pragma unroll
        for (int i = 0; i < CH; i++) {
            if (i > 0) CTRL_A(w0[i]);
            if (i + 2 < CH) { CTRL_D(w0[i+2]); LDD(dx[i+2], dy[i+2]); }
            float aw = fabsf(w0[i]);
            float g  = fmaf(dy[i], w1[i], dx[i] * aw);   // grad_f = e[m]*w0 + e[m+1]*w1
            bu[i] = fmaf(MOM, bu[i], g);
            sp[i] = fmaxf(fmaf(-LR, bu[i], sp[i]), 0.f);
            a0 = fmaf(sp[i], aw,    a0);                 // forward for next iteration
            a1 = fmaf(sp[i], w1[i], a1);
        }
        sts_f32(aaddr + eo0, a0);
        sts_f32(aaddr + eo1, a1);
        ROWBAR();
    }

    // ---- epilogue: stage rows, write (B,F,T) as float2 per (f, t-pair) ----
    __syncthreads();               // whole CTA done before union reuse
    {
        float* stg = &S.stage[rr][0];
        #pragma unroll
        for (int i = 0; i < CH; i++) stg[f_lo + i] = sp[i];
    }
    __syncthreads();
    {
        const int rb = blockIdx.x * RPB;
        const int t0 = rb & (TIME - 1);
        const int bb = rb >> 10;
        float* ob = out + (size_t)bb * N_STFT * TIME + t0;
        #pragma unroll 1
        for (int f = tid; f < N_STFT; f += THREADS) {
            float2 v = make_float2(S.stage[0][f], S.stage[1][f]);
            *reinterpret_cast<float2*>(ob + (size_t)f * TIME) = v;
        }
    }
}

// ---------------- launch ----------------
extern "C" void kernel_launch(void* const* d_in, const int* in_sizes, int n_in,
                              void* d_out, int out_size) {
    const float* mel = nullptr;   // 4*128*1024
    const float* spi = nullptr;   // 4*1024*1025
    const float* fb  = nullptr;   // 1025*128
    for (int i = 0; i < n_in; i++) {
        if      (in_sizes[i] == BATCH * N_MELS * TIME) mel = (const float*)d_in[i];
        else if (in_sizes[i] == ROWS * N_STFT)         spi = (const float*)d_in[i];
        else if (in_sizes[i] == N_STFT * N_MELS)       fb  = (const float*)d_in[i];
    }
    float* out = (float*)d_out;

    build_tables_k<<<(FPAD*32)/256, 256>>>(fb);   // warp per frequency
    imel_k<<<ROWS/RPB, THREADS>>>(mel, spi, out);
}

// round 8
// speedup vs baseline: 1.5857x; 1.5857x over previous
#include <cuda_runtime.h>
#include <cstdint>

#define N_STFT   1025
#define N_MELS   128
#define BATCH    4
#define TIME     1024
#define ROWS     (BATCH*TIME)
#define MAX_ITER 20
#define LR       0.3f
#define MOM      0.9f
#define INVC     (2.0f/4096.0f)
#define CH       33            // bins per lane (32*33 = 1056 >= 1025)
#define WPB      4             // warps (rows) per CTA
#define THREADS  (WPB*32)
#define FPAD     (32*CH)       // 1056
#define NENT     132           // entries: virtual mels -1..130 -> idx 0..131

// ---------------- device globals ----------------
// aw = |weight| of entry-mel; me = virtual mel + 1 (0..129); w1 = 1 - aw implied.
__device__ float         g_aw[FPAD];
__device__ unsigned char g_me[FPAD];

// ---------------- table build: one warp per frequency ----------------
__global__ void build_tables_k(const float* __restrict__ fb) {
    int gw   = (blockIdx.x * blockDim.x + threadIdx.x) >> 5;
    int lane = threadIdx.x & 31;
    if (gw >= FPAD) return;
    if (gw >= N_STFT) {                       // pad bins: top-dead
        if (!lane) { g_aw[gw] = 1.0f; g_me[gw] = 129; }
        return;
    }
    const float* r = fb + (size_t)gw * N_MELS;
    int m4 = lane * 4;
    unsigned loc = 128u;
    #pragma unroll
    for (int k = 3; k >= 0; k--) if (r[m4 + k] != 0.f) loc = (unsigned)(m4 + k);
    #pragma unroll
    for (int o = 16; o; o >>= 1) {
        unsigned v = __shfl_xor_sync(0xffffffffu, loc, o);
        loc = v < loc ? v : loc;
    }
    if (!lane) {
        float aw; int me;
        if (loc >= 128u) {                    // all-zero row: f=0 or f=1024
            aw = 1.0f; me = (gw == 0) ? 0 : 129;
        } else {
            int m0 = (int)loc;
            float w0raw = r[m0];
            float w1raw = (m0 < N_MELS - 1) ? r[m0 + 1] : 0.f;
            if (m0 == 0 && w1raw == 0.f && w0raw < 1.0f) {
                me = 0;                        // ascending-only region: virtual mel -1
                aw = fmaxf(1.0f - w0raw, 1e-6f);
            } else {
                me = m0 + 1; aw = w0raw;       // w1 = 1 - aw (exact overlap identity)
            }
        }
        g_aw[gw] = aw; g_me[gw] = (unsigned char)me;
    }
}

// ---------------- asm helpers ----------------
__device__ __forceinline__ unsigned smaddr(const void* p) {
    return (unsigned)__cvta_generic_to_shared(p);
}
__device__ __forceinline__ void sts_f32(unsigned a, float v) {
    asm volatile("st.shared.f32 [%0], %1;" :: "r"(a), "f"(v) : "memory");
}
// Entry layout (24 B): {e2x, e2y, acc0, acc1, acc2, pad}.
// On mel change (sign(w0) < 0): flush a0 -> acc0 of completed entry, shift
// a0<-a1, a1<-0, load next entry's diff pair into (d0,d1), advance cursor.
#define CTRL_FULL(w0i) asm volatile(                     \
    "{\n\t.reg .pred p;\n\t"                             \
    "setp.lt.f32 p, %5, 0f00000000;\n\t"                 \
    "@p st.shared.f32 [%0+8], %1;\n\t"                   \
    "selp.f32 %1, %2, %1, p;\n\t"                        \
    "selp.f32 %2, 0f00000000, %2, p;\n\t"                \
    "@p ld.shared.v2.f32 {%3,%4}, [%0+24];\n\t"          \
    "@p add.u32 %0, %0, 24;\n\t}"                        \
    : "+r"(addr), "+f"(a0), "+f"(a1), "+f"(d0), "+f"(d1) \
    : "f"(w0i) : "memory")
// forward-only variant (prologue)
#define CTRL_FWD(w0i) asm volatile(                      \
    "{\n\t.reg .pred p;\n\t"                             \
    "setp.lt.f32 p, %3, 0f00000000;\n\t"                 \
    "@p st.shared.f32 [%0+8], %1;\n\t"                   \
    "selp.f32 %1, %2, %1, p;\n\t"                        \
    "selp.f32 %2, 0f00000000, %2, p;\n\t"                \
    "@p add.u32 %0, %0, 24;\n\t}"                        \
    : "+r"(addr), "+f"(a0), "+f"(a1)                     \
    : "f"(w0i) : "memory")

// ---------------- shared: iteration phase / epilogue stage union ----------------
struct __align__(16) SmemIter {
    float ent[WPB][NENT][6];   // 24 B per entry, zero-initialized once
};
union __align__(16) SmemU {
    SmemIter it;
    float    stage[WPB][FPAD];
};

// ---------------- main: warp = one (b,t) row; 20 fused iterations ----------------
__global__ void __launch_bounds__(THREADS, 4)
imel_k(const float* __restrict__ mel, const float* __restrict__ spi,
       float* __restrict__ out)
{
    __shared__ SmemU S;
    const int tid  = threadIdx.x;
    const int wid  = tid >> 5;
    const int lane = tid & 31;
    const int row  = blockIdx.x * WPB + wid;
    const int b    = row >> 10;
    const int t    = row & (TIME - 1);

    // one-time zero of all entries (write pattern is static across iterations)
    {
        float4  z  = make_float4(0.f, 0.f, 0.f, 0.f);
        float4* pz = reinterpret_cast<float4*>(&S.it.ent[0][0][0]);
        #pragma unroll 1
        for (int k = tid; k < WPB*NENT*6/4; k += THREADS) pz[k] = z;
    }

    const int f_lo = lane * CH;

    // register state; sign(w0[i]) = "mel changes between bin i-1 and i"
    float w0[CH], sp[CH], bu[CH];
    int me0, pme = 0;
    #pragma unroll
    for (int i = 0; i < CH; i++) {
        int f  = f_lo + i;
        int fc = f > N_STFT-1 ? N_STFT-1 : f;
        float aw = g_aw[f];
        int   me = (int)g_me[f];
        sp[i] = spi[(size_t)row * N_STFT + fc];
        bu[i] = 0.f;
        if (i == 0) { me0 = me; w0[0] = aw; }
        else        { w0[i] = (me != pme) ? -aw : aw; }
        pme = me;
    }
    float melI[4];
    #pragma unroll
    for (int j = 0; j < 4; j++)
        melI[j] = mel[(size_t)b*(N_MELS*TIME) + (size_t)(lane + 32*j)*TIME + t] * INVC;

    const unsigned entb = smaddr(&S.it.ent[wid][0][0]);

    __syncthreads();   // zeros visible (block-wide init)

    // ---- prologue forward: scatter proj of iteration 0 ----
    {
        unsigned addr = entb + (unsigned)me0 * 24u;
        float a0 = 0.f, a1 = 0.f;
        #pragma unroll
        for (int i = 0; i < CH; i++) {
            if (i > 0) CTRL_FWD(w0[i]);
            float aw = fabsf(w0[i]);
            a0 = fmaf(sp[i], aw, a0);
            a1 = fmaf(sp[i], 1.0f - aw, a1);
        }
        sts_f32(addr + 12u, a0);   // acc1 of end entry
        sts_f32(addr + 40u, a1);   // acc2 of end entry + 1
    }
    __syncwarp();

    #pragma unroll 1
    for (int it = 0; it < MAX_ITER; it++) {
        // ---- combine: e[m] = INVC*proj[m] - INVC*mel[m]; pair rep (e2x,e2y) ----
        #pragma unroll
        for (int j = 0; j < 4; j++) {
            int m = lane + 32*j;
            unsigned ea = entb + (unsigned)(m + 1) * 24u;
            float x0, x1, x2;
            asm volatile("ld.shared.v2.f32 {%0,%1}, [%2+8];"
                         : "=f"(x0), "=f"(x1) : "r"(ea));
            asm volatile("ld.shared.f32 %0, [%1+16];" : "=f"(x2) : "r"(ea));
            float e = fmaf((x0 + x1) + x2, INVC, -melI[j]);
            sts_f32(ea, e);          // e2x of entry m+1 = e[m]
            sts_f32(ea - 20u, e);    // e2y of entry m   = e[m]
        }
        __syncwarp();

        // ---- fused backward(it) + forward(it+1) ----
        unsigned addr = entb + (unsigned)me0 * 24u;
        float d0, d1;
        asm volatile("ld.shared.v2.f32 {%0,%1}, [%2];"
                     : "=f"(d0), "=f"(d1) : "r"(addr));
        float a0 = 0.f, a1 = 0.f;
        #pragma unroll
        for (int i = 0; i < CH; i++) {
            if (i > 0) CTRL_FULL(w0[i]);
            float aw = fabsf(w0[i]);
            float g  = fmaf(aw, d0 - d1, d1);     // e[v]*aw + e[v+1]*(1-aw)
            bu[i] = fmaf(MOM, bu[i], g);
            sp[i] = fmaxf(fmaf(-LR, bu[i], sp[i]), 0.f);
            a0 = fmaf(sp[i], aw, a0);             // forward for next iteration
            a1 = fmaf(sp[i], 1.0f - aw, a1);
        }
        sts_f32(addr + 12u, a0);
        sts_f32(addr + 40u, a1);
        __syncwarp();
    }

    // ---- epilogue: stage rows in shared, write (B,F,T) with STG.128 ----
    __syncthreads();               // all warps done with union before reuse
    {
        float* stg = &S.stage[wid][0];
        #pragma unroll
        for (int i = 0; i < CH; i++) stg[f_lo + i] = sp[i];
    }
    __syncthreads();
    {
        const int rb = blockIdx.x * WPB;
        const int t0 = rb & (TIME - 1);
        const int bb = rb >> 10;
        float4* ob = reinterpret_cast<float4*>(out + (size_t)bb * N_STFT * TIME + t0);
        #pragma unroll 1
        for (int f = tid; f < N_STFT; f += THREADS) {
            float4 v = make_float4(S.stage[0][f], S.stage[1][f],
                                   S.stage[2][f], S.stage[3][f]);
            ob[(size_t)f * (TIME/4)] = v;
        }
    }
}

// ---------------- launch ----------------
extern "C" void kernel_launch(void* const* d_in, const int* in_sizes, int n_in,
                              void* d_out, int out_size) {
    const float* mel = nullptr;   // 4*128*1024
    const float* spi = nullptr;   // 4*1024*1025
    const float* fb  = nullptr;   // 1025*128
    for (int i = 0; i < n_in; i++) {
        if      (in_sizes[i] == BATCH * N_MELS * TIME) mel = (const float*)d_in[i];
        else if (in_sizes[i] == ROWS * N_STFT)         spi = (const float*)d_in[i];
        else if (in_sizes[i] == N_STFT * N_MELS)       fb  = (const float*)d_in[i];
    }
    float* out = (float*)d_out;

    build_tables_k<<<(FPAD*32 + 255)/256, 256>>>(fb);   // warp per frequency
    imel_k<<<ROWS/WPB, THREADS>>>(mel, spi, out);
}